// round 1
// baseline (speedup 1.0000x reference)
#include <cuda_runtime.h>
#include <cuda_bf16.h>
#include <cstdint>

// Problem constants
#define Bc   2
#define Lc   2048
#define Dc   1024
#define Hc   16
#define DKc  64

#define NEGF (-3.4028235e38f)

// ---------------------------------------------------------------------------
// Scratch (device globals — no allocation allowed)
// ---------------------------------------------------------------------------
__device__ float g_Q[Bc * Hc * Lc * DKc];   // [b,h,l,dk]
__device__ float g_K[Bc * Hc * Lc * DKc];
__device__ float g_V[Bc * Hc * Lc * DKc];
__device__ float g_AO[Bc * Lc * Dc];        // [b,l,h*dk]

// ---------------------------------------------------------------------------
// SGEMM  C[m][n] = sum_d A[m][d] * Bw[n][d]   (both K-contiguous, "NT")
// 128x128 tile, BK=16, 256 threads, 8x8 per thread.
// scatter==1: write C[m][n] to [b,h,l,dk] layout (m=b*L+l, n=h*64+dk)
// ---------------------------------------------------------------------------
#define GBM 128
#define GBN 128
#define GBK 16
#define GLDS 132   // padded stride (16B-aligned, 2-way worst-case conflicts)

__global__ __launch_bounds__(256)
void sgemm_nt(const float* __restrict__ A, const float* __restrict__ Bw,
              float* __restrict__ C, int M, int N, int K, int scatter)
{
    __shared__ float As[GBK * GLDS];
    __shared__ float Bs[GBK * GLDS];

    const int t  = threadIdx.x;
    const int m0 = blockIdx.y * GBM;
    const int n0 = blockIdx.x * GBN;
    const int tx = t & 15;
    const int ty = t >> 4;

    const int row_a = t >> 2;        // 0..63
    const int kq    = (t & 3) * 4;   // 0,4,8,12

    float acc[8][8];
#pragma unroll
    for (int i = 0; i < 8; ++i)
#pragma unroll
        for (int j = 0; j < 8; ++j) acc[i][j] = 0.f;

    for (int kb = 0; kb < K; kb += GBK) {
#pragma unroll
        for (int p = 0; p < 2; ++p) {
            int r = row_a + p * 64;
            float4 va = *(const float4*)&A[(size_t)(m0 + r) * K + kb + kq];
            As[(kq + 0) * GLDS + r] = va.x;
            As[(kq + 1) * GLDS + r] = va.y;
            As[(kq + 2) * GLDS + r] = va.z;
            As[(kq + 3) * GLDS + r] = va.w;
            float4 vb = *(const float4*)&Bw[(size_t)(n0 + r) * K + kb + kq];
            Bs[(kq + 0) * GLDS + r] = vb.x;
            Bs[(kq + 1) * GLDS + r] = vb.y;
            Bs[(kq + 2) * GLDS + r] = vb.z;
            Bs[(kq + 3) * GLDS + r] = vb.w;
        }
        __syncthreads();

#pragma unroll
        for (int kk = 0; kk < GBK; ++kk) {
            float4 a0 = *(const float4*)&As[kk * GLDS + ty * 4];
            float4 a1 = *(const float4*)&As[kk * GLDS + ty * 4 + 64];
            float4 b0 = *(const float4*)&Bs[kk * GLDS + tx * 4];
            float4 b1 = *(const float4*)&Bs[kk * GLDS + tx * 4 + 64];
            float av[8] = {a0.x, a0.y, a0.z, a0.w, a1.x, a1.y, a1.z, a1.w};
            float bv[8] = {b0.x, b0.y, b0.z, b0.w, b1.x, b1.y, b1.z, b1.w};
#pragma unroll
            for (int i = 0; i < 8; ++i)
#pragma unroll
                for (int j = 0; j < 8; ++j)
                    acc[i][j] = fmaf(av[i], bv[j], acc[i][j]);
        }
        __syncthreads();
    }

    // epilogue
#pragma unroll
    for (int ig = 0; ig < 2; ++ig)
#pragma unroll
        for (int i = 0; i < 4; ++i) {
            int m = m0 + ig * 64 + ty * 4 + i;
#pragma unroll
            for (int jg = 0; jg < 2; ++jg)
#pragma unroll
                for (int j = 0; j < 4; ++j) {
                    int n = n0 + jg * 64 + tx * 4 + j;
                    float v = acc[ig * 4 + i][jg * 4 + j];
                    if (!scatter) {
                        C[(size_t)m * N + n] = v;
                    } else {
                        int b  = m >> 11;          // /L
                        int l  = m & (Lc - 1);
                        int h  = n >> 6;           // /DK
                        int dk = n & 63;
                        C[(((size_t)b * Hc + h) * Lc + l) * DKc + dk] = v;
                    }
                }
        }
}

// ---------------------------------------------------------------------------
// Fused attention: per block = one (b,h) and 16 queries.
//  Phase S : S = Q K^T / 8 (masked) into shared (16 x 2048)
//  Phase E : 1.5-entmax per row, bisection on tau, row in registers
//  Phase PV: out = P V  (split-K over 2 thread-halves)
// ---------------------------------------------------------------------------
#define TQ  16
#define SP  2064     // padded row stride of S (2048+16): conflict-free access
#define KC  128      // K/V staging chunk rows
#define ATT_SMEM ((TQ*SP + TQ*65 + KC*65) * 4)

__global__ __launch_bounds__(256)
void attn_entmax_kernel(const float* __restrict__ Qp, const float* __restrict__ Kp,
                        const float* __restrict__ Vp, const int* __restrict__ maskp,
                        float* __restrict__ AO)
{
    extern __shared__ float sm[];
    float* Ssh  = sm;                 // TQ * SP
    float* Qsh  = sm + TQ * SP;       // TQ * 65
    float* KVsh = Qsh + TQ * 65;      // KC * 65

    const int t  = threadIdx.x;
    const int q0 = blockIdx.x * TQ;
    const int h  = blockIdx.y;
    const int b  = blockIdx.z;
    const int bh = b * Hc + h;

    const float* Qg = Qp + ((size_t)bh * Lc + q0) * DKc;
    const float* Kg = Kp + (size_t)bh * Lc * DKc;
    const float* Vg = Vp + (size_t)bh * Lc * DKc;

    // ---- load Q tile ----
    for (int i = t; i < TQ * DKc; i += 256) {
        int qi = i >> 6, d = i & 63;
        Qsh[qi * 65 + d] = Qg[i];
    }

    const int tyq = t >> 5;           // 0..7 (constant per warp)
    const int txk = t & 31;
    const int qiA = 2 * tyq;

    // ---- Phase S ----
    for (int kb = 0; kb < Lc; kb += KC) {
        __syncthreads();
        {
            const float4* src = (const float4*)(Kg + (size_t)kb * DKc);
            for (int i = t; i < KC * 16; i += 256) {
                int r = i >> 4, c = i & 15;
                float4 v = src[r * 16 + c];
                float* dst = &KVsh[r * 65 + c * 4];
                dst[0] = v.x; dst[1] = v.y; dst[2] = v.z; dst[3] = v.w;
            }
        }
        __syncthreads();

        float acc[2][4] = {{0.f,0.f,0.f,0.f},{0.f,0.f,0.f,0.f}};
#pragma unroll 8
        for (int d = 0; d < 64; ++d) {
            float qa = Qsh[qiA * 65 + d];
            float qb = Qsh[(qiA + 1) * 65 + d];
#pragma unroll
            for (int j = 0; j < 4; ++j) {
                float kv = KVsh[(txk + 32 * j) * 65 + d];
                acc[0][j] = fmaf(qa, kv, acc[0][j]);
                acc[1][j] = fmaf(qb, kv, acc[1][j]);
            }
        }
#pragma unroll
        for (int i = 0; i < 2; ++i) {
            const int* mrow = maskp + ((size_t)b * Lc + q0 + qiA + i) * Lc;
#pragma unroll
            for (int j = 0; j < 4; ++j) {
                int k = kb + txk + 32 * j;
                int mv = mrow[k];
                Ssh[(qiA + i) * SP + k] = mv ? acc[i][j] * 0.125f : NEGF;
            }
        }
    }
    __syncthreads();

    // ---- Phase E: entmax15, warp per row (2 rows/warp) ----
    {
        const int warp = t >> 5, lane = t & 31;
        for (int r = 0; r < 2; ++r) {
            int qi = warp * 2 + r;
            float* Srow = &Ssh[qi * SP];
            float z[64];
            float mx = NEGF;
#pragma unroll
            for (int u = 0; u < 64; ++u) {
                z[u] = Srow[lane + 32 * u];
                mx = fmaxf(mx, z[u]);
            }
#pragma unroll
            for (int off = 16; off; off >>= 1)
                mx = fmaxf(mx, __shfl_xor_sync(0xffffffffu, mx, off));
#pragma unroll
            for (int u = 0; u < 64; ++u) z[u] = (z[u] - mx) * 0.5f;

            float lo = -1.0f, hi = 0.0f;
            for (int it = 0; it < 28; ++it) {
                float tau = 0.5f * (lo + hi);
                float s = 0.f;
#pragma unroll
                for (int u = 0; u < 64; ++u) {
                    float d = fmaxf(z[u] - tau, 0.f);
                    s = fmaf(d, d, s);
                }
#pragma unroll
                for (int off = 16; off; off >>= 1)
                    s += __shfl_xor_sync(0xffffffffu, s, off);
                if (s >= 1.0f) lo = tau; else hi = tau;
            }
            float tau = 0.5f * (lo + hi);
#pragma unroll
            for (int u = 0; u < 64; ++u) {
                float d = fmaxf(z[u] - tau, 0.f);
                Srow[lane + 32 * u] = d * d;
            }
        }
    }
    __syncthreads();

    // ---- Phase PV (split-K over 2 halves of the block) ----
    const int half = t >> 7;          // 0: k in [0,1024), 1: k in [1024,2048)
    const int tt   = t & 127;
    const int ptyq = tt >> 4;         // 0..7  -> qi = 2*ptyq, 2*ptyq+1
    const int ptxd = tt & 15;         // d = ptxd + 16*j

    float pacc[2][4] = {{0.f,0.f,0.f,0.f},{0.f,0.f,0.f,0.f}};

    for (int kb0 = 0; kb0 < 1024; kb0 += 64) {
        __syncthreads();
        // stage rows 0..63 -> k = kb0+r ; rows 64..127 -> k = 1024+kb0+(r-64)
        for (int i = t; i < 128 * 16; i += 256) {
            int r = i >> 4, c = i & 15;
            int kg = (r < 64) ? (kb0 + r) : (1024 + kb0 + r - 64);
            float4 v = *(const float4*)(Vg + (size_t)kg * 64 + c * 4);
            float* dst = &KVsh[r * 65 + c * 4];
            dst[0] = v.x; dst[1] = v.y; dst[2] = v.z; dst[3] = v.w;
        }
        __syncthreads();

#pragma unroll 4
        for (int kk = 0; kk < 64; ++kk) {
            int kloc = half * 64 + kk;
            int k    = half * 1024 + kb0 + kk;
            float s0 = Ssh[(2 * ptyq) * SP + k];
            float s1 = Ssh[(2 * ptyq + 1) * SP + k];
#pragma unroll
            for (int j = 0; j < 4; ++j) {
                float v = KVsh[kloc * 65 + ptxd + 16 * j];
                pacc[0][j] = fmaf(s0, v, pacc[0][j]);
                pacc[1][j] = fmaf(s1, v, pacc[1][j]);
            }
        }
    }
    __syncthreads();

    // reduce the two halves through Qsh (Q no longer needed)
    if (half == 1) {
#pragma unroll
        for (int i = 0; i < 2; ++i)
#pragma unroll
            for (int j = 0; j < 4; ++j)
                Qsh[(2 * ptyq + i) * 64 + ptxd + 16 * j] = pacc[i][j];
    }
    __syncthreads();
    if (half == 0) {
#pragma unroll
        for (int i = 0; i < 2; ++i) {
            int qi = 2 * ptyq + i;
            float* orow = AO + ((size_t)b * Lc + q0 + qi) * Dc + h * DKc;
#pragma unroll
            for (int j = 0; j < 4; ++j) {
                int d = ptxd + 16 * j;
                orow[d] = pacc[i][j] + Qsh[qi * 64 + d];
            }
        }
    }
}

// ---------------------------------------------------------------------------
// Launch
// ---------------------------------------------------------------------------
extern "C" void kernel_launch(void* const* d_in, const int* in_sizes, int n_in,
                              void* d_out, int out_size)
{
    const float* q    = (const float*)d_in[0];
    const float* k    = (const float*)d_in[1];
    const float* v    = (const float*)d_in[2];
    const int*   mask = (const int*)  d_in[3];
    const float* w_q  = (const float*)d_in[4];
    const float* w_k  = (const float*)d_in[5];
    const float* w_v  = (const float*)d_in[6];
    const float* w_o  = (const float*)d_in[7];
    float* out = (float*)d_out;

    float *gQ, *gK, *gV, *gA;
    cudaGetSymbolAddress((void**)&gQ, g_Q);
    cudaGetSymbolAddress((void**)&gK, g_K);
    cudaGetSymbolAddress((void**)&gV, g_V);
    cudaGetSymbolAddress((void**)&gA, g_AO);

    const int M = Bc * Lc;   // 4096
    const int N = Dc;        // 1024
    const int K = Dc;        // 1024
    dim3 gg(N / GBN, M / GBM);

    sgemm_nt<<<gg, 256>>>(q, w_q, gQ, M, N, K, 1);
    sgemm_nt<<<gg, 256>>>(k, w_k, gK, M, N, K, 1);
    sgemm_nt<<<gg, 256>>>(v, w_v, gV, M, N, K, 1);

    cudaFuncSetAttribute(attn_entmax_kernel,
                         cudaFuncAttributeMaxDynamicSharedMemorySize, ATT_SMEM);
    attn_entmax_kernel<<<dim3(Lc / TQ, Hc, Bc), 256, ATT_SMEM>>>(gQ, gK, gV, mask, gA);

    sgemm_nt<<<gg, 256>>>(gA, w_o, out, M, N, K, 0);
}

// round 3
// speedup vs baseline: 1.1351x; 1.1351x over previous
#include <cuda_runtime.h>
#include <mma.h>
#include <cstdint>

using namespace nvcuda;

// Problem constants
#define Bc   2
#define Lc   2048
#define Dc   1024
#define Hc   16
#define DKc  64

#define NEGF (-3.4028235e38f)

// ---------------------------------------------------------------------------
// Scratch (device globals — no allocation allowed)
// ---------------------------------------------------------------------------
__device__ float g_Q[Bc * Hc * Lc * DKc];   // [b,h,l,dk]
__device__ float g_K[Bc * Hc * Lc * DKc];
__device__ float g_V[Bc * Hc * Lc * DKc];
__device__ float g_AO[Bc * Lc * Dc];        // [b,l,h*dk]

// Split a freshly-loaded fp32 fragment into tf32 hi + tf32 lo (3xTF32 trick).
template <typename Frag>
__device__ __forceinline__ void split_tf32(Frag& hi, Frag& lo) {
#pragma unroll
    for (int i = 0; i < hi.num_elements; ++i) {
        float x = hi.x[i];
        float h = wmma::__float_to_tf32(x);
        hi.x[i] = h;
        lo.x[i] = wmma::__float_to_tf32(x - h);
    }
}

// ---------------------------------------------------------------------------
// 3xTF32 GEMM  C[m][n] = sum_d A[m][d] * Bw[n][d]   ("NT": both K-contiguous)
// 128x128x32 block tile, 8 warps (4x2), warp tile 32x64, wmma m16n16k8.
// scatter==1: write C[m][n] into [b,h,l,dk] layout (m=b*L+l, n=h*64+dk)
// ---------------------------------------------------------------------------
#define PBM 128
#define PBN 128
#define PBK 32
#define PLDS 40

__global__ __launch_bounds__(256)
void gemm_3xtf32(const float* __restrict__ A, const float* __restrict__ Bw,
                 float* __restrict__ C, int M, int N, int K, int scatter)
{
    __shared__ float As[PBM * PLDS];
    __shared__ float Bs[PBN * PLDS];

    const int t    = threadIdx.x;
    const int warp = t >> 5;
    const int wm   = warp >> 1;       // 0..3
    const int wn   = warp & 1;        // 0..1
    const int m0   = blockIdx.y * PBM;
    const int n0   = blockIdx.x * PBN;

    wmma::fragment<wmma::accumulator, 16, 16, 8, float> acc[2][4];
#pragma unroll
    for (int i = 0; i < 2; ++i)
#pragma unroll
        for (int j = 0; j < 4; ++j) wmma::fill_fragment(acc[i][j], 0.0f);

    for (int kb = 0; kb < K; kb += PBK) {
#pragma unroll
        for (int f = 0; f < 4; ++f) {
            int idx = t + f * 256;            // 0..1023 float4 slots
            int row = idx >> 3;
            int c4  = idx & 7;
            float4 va = *(const float4*)&A [(size_t)(m0 + row) * K + kb + c4 * 4];
            *(float4*)&As[row * PLDS + c4 * 4] = va;
            float4 vb = *(const float4*)&Bw[(size_t)(n0 + row) * K + kb + c4 * 4];
            *(float4*)&Bs[row * PLDS + c4 * 4] = vb;
        }
        __syncthreads();

#pragma unroll
        for (int ks = 0; ks < 4; ++ks) {
            wmma::fragment<wmma::matrix_a, 16, 16, 8, wmma::precision::tf32, wmma::row_major> ah[2], al[2];
#pragma unroll
            for (int i = 0; i < 2; ++i) {
                wmma::load_matrix_sync(ah[i], &As[(wm * 32 + i * 16) * PLDS + ks * 8], PLDS);
                split_tf32(ah[i], al[i]);
            }
#pragma unroll
            for (int j = 0; j < 4; ++j) {
                wmma::fragment<wmma::matrix_b, 16, 16, 8, wmma::precision::tf32, wmma::col_major> bh, bl;
                wmma::load_matrix_sync(bh, &Bs[(wn * 64 + j * 16) * PLDS + ks * 8], PLDS);
                split_tf32(bh, bl);
#pragma unroll
                for (int i = 0; i < 2; ++i) {
                    wmma::mma_sync(acc[i][j], al[i], bh, acc[i][j]);
                    wmma::mma_sync(acc[i][j], ah[i], bl, acc[i][j]);
                    wmma::mma_sync(acc[i][j], ah[i], bh, acc[i][j]);
                }
            }
        }
        __syncthreads();
    }

#pragma unroll
    for (int i = 0; i < 2; ++i)
#pragma unroll
        for (int j = 0; j < 4; ++j) {
            int m = m0 + wm * 32 + i * 16;
            int n = n0 + wn * 64 + j * 16;
            if (!scatter) {
                wmma::store_matrix_sync(&C[(size_t)m * N + n], acc[i][j], N, wmma::mem_row_major);
            } else {
                int b  = m >> 11;
                int l  = m & (Lc - 1);
                int h  = n >> 6;
                int dk = n & 63;
                float* dst = &C[(((size_t)b * Hc + h) * Lc + l) * DKc + dk];
                wmma::store_matrix_sync(dst, acc[i][j], DKc, wmma::mem_row_major);
            }
        }
}

// ---------------------------------------------------------------------------
// Fused attention: block = one (b,h), 16 queries.
//  S  : 3xtf32 wmma, Q frags in regs, K frags straight from global; S -> shared
//  E  : mask/scale pass, then 1.5-entmax per row (Newton on tau, 8 iters)
//  PV : 3xtf32 wmma, P from shared, V frags from global, split-K over 2 halves
// ---------------------------------------------------------------------------
#define TQ  16
#define SP  2064          // padded row stride of S
#define RST 72            // reduction buffer stride
#define ATT_SMEM ((TQ * SP + 2 * TQ * RST) * 4)

__global__ __launch_bounds__(256)
void attn_entmax_kernel(const float* __restrict__ Qp, const float* __restrict__ Kp,
                        const float* __restrict__ Vp, const int* __restrict__ maskp,
                        float* __restrict__ AO)
{
    extern __shared__ float sm[];
    float* Ssh = sm;                   // TQ * SP
    float* Rsh = sm + TQ * SP;         // 2 * TQ * RST

    const int t    = threadIdx.x;
    const int warp = t >> 5;
    const int lane = t & 31;
    const int q0   = blockIdx.x * TQ;
    const int h    = blockIdx.y;
    const int b    = blockIdx.z;
    const int bh   = b * Hc + h;

    const float* Qg = Qp + ((size_t)bh * Lc + q0) * DKc;
    const float* Kg = Kp + (size_t)bh * Lc * DKc;
    const float* Vg = Vp + (size_t)bh * Lc * DKc;

    // ---- Phase S: S[16 x 2048] = Q K^T (3xtf32) ----
    {
        wmma::fragment<wmma::matrix_a, 16, 16, 8, wmma::precision::tf32, wmma::row_major> aqh[8], aql[8];
#pragma unroll
        for (int kf = 0; kf < 8; ++kf) {
            wmma::load_matrix_sync(aqh[kf], Qg + kf * 8, DKc);
            split_tf32(aqh[kf], aql[kf]);
        }
#pragma unroll 1
        for (int c = 0; c < 16; ++c) {
            int key0 = c * 128 + warp * 16;
            wmma::fragment<wmma::accumulator, 16, 16, 8, float> acc;
            wmma::fill_fragment(acc, 0.0f);
#pragma unroll
            for (int kf = 0; kf < 8; ++kf) {
                wmma::fragment<wmma::matrix_b, 16, 16, 8, wmma::precision::tf32, wmma::col_major> bkh, bkl;
                wmma::load_matrix_sync(bkh, Kg + (size_t)key0 * DKc + kf * 8, DKc);
                split_tf32(bkh, bkl);
                wmma::mma_sync(acc, aql[kf], bkh, acc);
                wmma::mma_sync(acc, aqh[kf], bkl, acc);
                wmma::mma_sync(acc, aqh[kf], bkh, acc);
            }
            wmma::store_matrix_sync(&Ssh[key0], acc, SP, wmma::mem_row_major);
        }
    }
    __syncthreads();

    // ---- mask + scale pass ----
    {
        const int* mbase = maskp + ((size_t)b * Lc + q0) * Lc;
#pragma unroll 4
        for (int f = t; f < TQ * Lc / 4; f += 256) {
            int row = f >> 9;         // 512 float4 per row
            int c4  = f & 511;
            float4 s = *(float4*)&Ssh[row * SP + c4 * 4];
            int4  mv = *(const int4*)&mbase[(size_t)row * Lc + c4 * 4];
            s.x = mv.x ? s.x * 0.125f : NEGF;
            s.y = mv.y ? s.y * 0.125f : NEGF;
            s.z = mv.z ? s.z * 0.125f : NEGF;
            s.w = mv.w ? s.w * 0.125f : NEGF;
            *(float4*)&Ssh[row * SP + c4 * 4] = s;
        }
    }
    __syncthreads();

    // ---- entmax15: warp per row (2 rows/warp), Newton on tau ----
    for (int r = 0; r < 2; ++r) {
        int qi = warp * 2 + r;
        float* Srow = &Ssh[qi * SP];
        float z[64];
        float mx = NEGF;
#pragma unroll
        for (int u = 0; u < 64; ++u) {
            z[u] = Srow[lane + 32 * u];
            mx = fmaxf(mx, z[u]);
        }
#pragma unroll
        for (int off = 16; off; off >>= 1)
            mx = fmaxf(mx, __shfl_xor_sync(0xffffffffu, mx, off));
#pragma unroll
        for (int u = 0; u < 64; ++u) z[u] = (z[u] - mx) * 0.5f;

        // Newton from tau0 = -1: f(tau)=sum (z-tau)_+^2 - 1 is convex decreasing,
        // root in [-1,0] -> monotone quadratic convergence from the left.
        float tau = -1.0f;
#pragma unroll 1
        for (int it = 0; it < 8; ++it) {
            float s = 0.f, s1 = 0.f;
#pragma unroll
            for (int u = 0; u < 64; ++u) {
                float d = fmaxf(z[u] - tau, 0.f);
                s  = fmaf(d, d, s);
                s1 += d;
            }
#pragma unroll
            for (int off = 16; off; off >>= 1) {
                s  += __shfl_xor_sync(0xffffffffu, s,  off);
                s1 += __shfl_xor_sync(0xffffffffu, s1, off);
            }
            tau += (s - 1.0f) / (2.0f * s1);
        }
#pragma unroll
        for (int u = 0; u < 64; ++u) {
            float d = fmaxf(z[u] - tau, 0.f);
            Srow[lane + 32 * u] = d * d;
        }
    }
    __syncthreads();

    // ---- Phase PV: out[16 x 64] = P V (3xtf32), split-K over 2 warp-halves ----
    {
        int khalf = warp >> 2;
        int d0    = (warp & 3) * 16;
        wmma::fragment<wmma::accumulator, 16, 16, 8, float> acc;
        wmma::fill_fragment(acc, 0.0f);
#pragma unroll 2
        for (int kf = 0; kf < 128; ++kf) {
            int k0 = khalf * 1024 + kf * 8;
            wmma::fragment<wmma::matrix_a, 16, 16, 8, wmma::precision::tf32, wmma::row_major> aph, apl;
            wmma::load_matrix_sync(aph, &Ssh[k0], SP);
            split_tf32(aph, apl);
            wmma::fragment<wmma::matrix_b, 16, 16, 8, wmma::precision::tf32, wmma::row_major> bvh, bvl;
            wmma::load_matrix_sync(bvh, Vg + (size_t)k0 * DKc + d0, DKc);
            split_tf32(bvh, bvl);
            wmma::mma_sync(acc, apl, bvh, acc);
            wmma::mma_sync(acc, aph, bvl, acc);
            wmma::mma_sync(acc, aph, bvh, acc);
        }
        wmma::store_matrix_sync(&Rsh[khalf * TQ * RST + d0], acc, RST, wmma::mem_row_major);
    }
    __syncthreads();

    // ---- reduce halves + write out ----
    {
        int qi = t >> 4;
        int c4 = t & 15;
        float4 r0 = *(float4*)&Rsh[qi * RST + c4 * 4];
        float4 r1 = *(float4*)&Rsh[TQ * RST + qi * RST + c4 * 4];
        float4 o;
        o.x = r0.x + r1.x; o.y = r0.y + r1.y; o.z = r0.z + r1.z; o.w = r0.w + r1.w;
        *(float4*)&AO[((size_t)b * Lc + q0 + qi) * Dc + h * DKc + c4 * 4] = o;
    }
}

// ---------------------------------------------------------------------------
// Launch
// ---------------------------------------------------------------------------
extern "C" void kernel_launch(void* const* d_in, const int* in_sizes, int n_in,
                              void* d_out, int out_size)
{
    const float* q    = (const float*)d_in[0];
    const float* k    = (const float*)d_in[1];
    const float* v    = (const float*)d_in[2];
    const int*   mask = (const int*)  d_in[3];
    const float* w_q  = (const float*)d_in[4];
    const float* w_k  = (const float*)d_in[5];
    const float* w_v  = (const float*)d_in[6];
    const float* w_o  = (const float*)d_in[7];
    float* out = (float*)d_out;

    float *gQ, *gK, *gV, *gA;
    cudaGetSymbolAddress((void**)&gQ, g_Q);
    cudaGetSymbolAddress((void**)&gK, g_K);
    cudaGetSymbolAddress((void**)&gV, g_V);
    cudaGetSymbolAddress((void**)&gA, g_AO);

    const int M = Bc * Lc;   // 4096
    const int N = Dc;        // 1024
    const int K = Dc;        // 1024
    dim3 gg(N / PBN, M / PBM);

    gemm_3xtf32<<<gg, 256>>>(q, w_q, gQ, M, N, K, 1);
    gemm_3xtf32<<<gg, 256>>>(k, w_k, gK, M, N, K, 1);
    gemm_3xtf32<<<gg, 256>>>(v, w_v, gV, M, N, K, 1);

    cudaFuncSetAttribute(attn_entmax_kernel,
                         cudaFuncAttributeMaxDynamicSharedMemorySize, ATT_SMEM);
    attn_entmax_kernel<<<dim3(Lc / TQ, Hc, Bc), 256, ATT_SMEM>>>(gQ, gK, gV, mask, gA);

    gemm_3xtf32<<<gg, 256>>>(gA, w_o, out, M, N, K, 0);
}

// round 5
// speedup vs baseline: 2.0210x; 1.7805x over previous
#include <cuda_runtime.h>
#include <cuda_bf16.h>
#include <mma.h>
#include <cstdint>

using namespace nvcuda;
typedef __nv_bfloat16 bf16;

// Problem constants
#define Bc   2
#define Lc   2048
#define Dc   1024
#define Hc   16
#define DKc  64
#define NEGF (-3.4028235e38f)

#define NEL (Bc * Lc * Dc)     // 4,194,304
#define NW  (Dc * Dc)          // 1,048,576

// ---------------------------------------------------------------------------
// Scratch (device globals — no allocation allowed)
// ---------------------------------------------------------------------------
__device__ bf16 g_qh[NEL], g_ql[NEL], g_kh[NEL], g_kl[NEL], g_vh[NEL], g_vl[NEL];
__device__ bf16 g_wqh[NW], g_wql[NW], g_wkh[NW], g_wkl[NW];
__device__ bf16 g_wvh[NW], g_wvl[NW], g_woh[NW], g_wol[NW];
__device__ bf16 g_Qh[NEL], g_Ql[NEL], g_Kh[NEL], g_Kl[NEL], g_Vh[NEL], g_Vl[NEL];
__device__ bf16 g_aoh[NEL], g_aol[NEL];

// ---------------------------------------------------------------------------
// Split fp32 -> bf16 hi + bf16 lo
// ---------------------------------------------------------------------------
__device__ __forceinline__ void split1(float x, bf16& h, bf16& l) {
    h = __float2bfloat16_rn(x);
    l = __float2bfloat16_rn(x - __bfloat162float(h));
}

__global__ void split_bf16(const float* __restrict__ x, bf16* __restrict__ hi,
                           bf16* __restrict__ lo, int n)
{
    int i = (blockIdx.x * blockDim.x + threadIdx.x) * 4;
    if (i >= n) return;
    float4 v = *(const float4*)(x + i);
    bf16 h0, h1, h2, h3, l0, l1, l2, l3;
    split1(v.x, h0, l0); split1(v.y, h1, l1);
    split1(v.z, h2, l2); split1(v.w, h3, l3);
    __nv_bfloat162* H = (__nv_bfloat162*)(hi + i);
    __nv_bfloat162* L = (__nv_bfloat162*)(lo + i);
    H[0] = __nv_bfloat162(h0, h1); H[1] = __nv_bfloat162(h2, h3);
    L[0] = __nv_bfloat162(l0, l1); L[1] = __nv_bfloat162(l2, l3);
}

// ---------------------------------------------------------------------------
// cp.async helpers
// ---------------------------------------------------------------------------
__device__ __forceinline__ void cp16(unsigned dst, const void* src) {
    asm volatile("cp.async.cg.shared.global [%0], [%1], 16;" :: "r"(dst), "l"(src));
}
#define CP_COMMIT() asm volatile("cp.async.commit_group;")
#define CP_WAIT(n)  asm volatile("cp.async.wait_group %0;" :: "n"(n))

// ---------------------------------------------------------------------------
// bf16x3 GEMM  C[m][n] = sum_d A[m][d] * Bw[n][d]   (NT, K = N = 1024, M = 4096)
// 128x128x32 tile, 8 warps (4x2), warp 32x64, wmma m16n16k16, double-buffered
// cp.async. scatter==1: emit hi/lo bf16 into [b,h,l,dk]; else fp32 C.
// ---------------------------------------------------------------------------
#define KK     1024
#define SAL    40            // smem row stride (bf16 elems)
#define AB_EL  (128 * SAL)   // 5120 bf16 per tile
#define STG_EL (4 * AB_EL)   // 20480 bf16 per stage
#define GEMM_SMEM (2 * STG_EL * 2)   // 81,920 bytes

__global__ __launch_bounds__(256)
void gemm_bf16x3(const bf16* __restrict__ Ah, const bf16* __restrict__ Al,
                 const bf16* __restrict__ Bh, const bf16* __restrict__ Bl,
                 float* __restrict__ C, bf16* __restrict__ Ch, bf16* __restrict__ Cl,
                 int scatter)
{
    extern __shared__ char dsm[];
    bf16*  smem = (bf16*)dsm;
    float* epi  = (float*)dsm;
    const unsigned sbase = (unsigned)__cvta_generic_to_shared(dsm);

    const int t    = threadIdx.x;
    const int warp = t >> 5;
    const int wm   = warp >> 1;
    const int wn   = warp & 1;
    const int m0   = blockIdx.y * 128;
    const int n0   = blockIdx.x * 128;

    const bf16* gsrc[4] = { Ah + (size_t)m0 * KK, Al + (size_t)m0 * KK,
                            Bh + (size_t)n0 * KK, Bl + (size_t)n0 * KK };

    wmma::fragment<wmma::accumulator, 16, 16, 16, float> acc[2][4];
#pragma unroll
    for (int i = 0; i < 2; ++i)
#pragma unroll
        for (int j = 0; j < 4; ++j) wmma::fill_fragment(acc[i][j], 0.0f);

    auto prefetch = [&](int s, int kb) {
#pragma unroll
        for (int a = 0; a < 4; ++a)
#pragma unroll
            for (int rep = 0; rep < 2; ++rep) {
                int chunk = t + rep * 256;      // 0..511
                int row = chunk >> 2, seg = chunk & 3;
                cp16(sbase + (unsigned)(s * STG_EL + a * AB_EL + row * SAL + seg * 8) * 2,
                     gsrc[a] + (size_t)row * KK + kb + seg * 8);
            }
        CP_COMMIT();
    };

    prefetch(0, 0);

    for (int it = 0; it < KK / 32; ++it) {
        int s = it & 1;
        if (it + 1 < KK / 32) { prefetch(s ^ 1, (it + 1) * 32); CP_WAIT(1); }
        else                  { CP_WAIT(0); }
        __syncthreads();

        const bf16* sAh = smem + s * STG_EL;
        const bf16* sAl = sAh + AB_EL;
        const bf16* sBh = sAl + AB_EL;
        const bf16* sBl = sBh + AB_EL;

#pragma unroll
        for (int ks = 0; ks < 32; ks += 16) {
            wmma::fragment<wmma::matrix_a, 16, 16, 16, bf16, wmma::row_major> ah[2], al[2];
#pragma unroll
            for (int i = 0; i < 2; ++i) {
                wmma::load_matrix_sync(ah[i], &sAh[(wm * 32 + i * 16) * SAL + ks], SAL);
                wmma::load_matrix_sync(al[i], &sAl[(wm * 32 + i * 16) * SAL + ks], SAL);
            }
#pragma unroll
            for (int j = 0; j < 4; ++j) {
                wmma::fragment<wmma::matrix_b, 16, 16, 16, bf16, wmma::col_major> bh, bl;
                wmma::load_matrix_sync(bh, &sBh[(wn * 64 + j * 16) * SAL + ks], SAL);
                wmma::load_matrix_sync(bl, &sBl[(wn * 64 + j * 16) * SAL + ks], SAL);
#pragma unroll
                for (int i = 0; i < 2; ++i) {
                    wmma::mma_sync(acc[i][j], al[i], bh, acc[i][j]);
                    wmma::mma_sync(acc[i][j], ah[i], bl, acc[i][j]);
                    wmma::mma_sync(acc[i][j], ah[i], bh, acc[i][j]);
                }
            }
        }
        __syncthreads();
    }

    // epilogue via fp32 smem buffer (stride 132); smem bytes are free now
    __syncthreads();
#pragma unroll
    for (int i = 0; i < 2; ++i)
#pragma unroll
        for (int j = 0; j < 4; ++j)
            wmma::store_matrix_sync(&epi[(wm * 32 + i * 16) * 132 + wn * 64 + j * 16],
                                    acc[i][j], 132, wmma::mem_row_major);
    __syncthreads();

#pragma unroll
    for (int f = 0; f < 16; ++f) {
        int idx = t + f * 256;              // 0..4095 float4 slots
        int row = idx >> 5, c4 = idx & 31;
        float4 v = *(float4*)&epi[row * 132 + c4 * 4];
        int m = m0 + row, n = n0 + c4 * 4;
        if (!scatter) {
            *(float4*)&C[(size_t)m * Dc + n] = v;
        } else {
            int b = m >> 11, l = m & (Lc - 1);
            int h = n >> 6,  dk = n & 63;
            size_t o = (((size_t)b * Hc + h) * Lc + l) * DKc + dk;
            bf16 h0, h1, h2, h3, l0, l1, l2, l3;
            split1(v.x, h0, l0); split1(v.y, h1, l1);
            split1(v.z, h2, l2); split1(v.w, h3, l3);
            *(__nv_bfloat162*)&Ch[o]     = __nv_bfloat162(h0, h1);
            *(__nv_bfloat162*)&Ch[o + 2] = __nv_bfloat162(h2, h3);
            *(__nv_bfloat162*)&Cl[o]     = __nv_bfloat162(l0, l1);
            *(__nv_bfloat162*)&Cl[o + 2] = __nv_bfloat162(l2, l3);
        }
    }
}

// ---------------------------------------------------------------------------
// Fused attention: block = one (b,h), 16 queries.
//  S  : bf16x3 wmma, Q frags in regs, K frags from global; S (fp32) -> shared
//  E  : mask/scale, then 1.5-entmax per row (Newton, 8 iters); emits P hi/lo
//       bf16 (Phi in-place over S, Plo in own buffer)
//  PV : bf16x3 wmma, P from shared, V frags from global, split-K x2
// ---------------------------------------------------------------------------
#define SP   2052            // fp32 S row stride (2052 % 32 == 4: conflict-free)
#define PLOP 2056            // Plo bf16 row stride
#define RST  72
#define ATT_SMEM (16 * SP * 4 + 16 * PLOP * 2 + 2 * 16 * RST * 4)   // 206,336 B

__global__ __launch_bounds__(256)
void attn_entmax_kernel(const bf16* __restrict__ Qh, const bf16* __restrict__ Ql,
                        const bf16* __restrict__ Kh, const bf16* __restrict__ Kl,
                        const bf16* __restrict__ Vh, const bf16* __restrict__ Vl,
                        const int* __restrict__ maskp,
                        bf16* __restrict__ AOh, bf16* __restrict__ AOl)
{
    extern __shared__ float sm[];
    float* Ssh  = sm;                                    // 16 x SP fp32
    bf16*  PloS = (bf16*)(sm + 16 * SP);                 // 16 x PLOP bf16
    float* Rsh  = (float*)((char*)PloS + 16 * PLOP * 2); // 2 x 16 x RST fp32

    const int t    = threadIdx.x;
    const int warp = t >> 5;
    const int lane = t & 31;
    const int q0   = blockIdx.x * 16;
    const int h    = blockIdx.y;
    const int b    = blockIdx.z;
    const int bh   = b * Hc + h;

    const bf16* Qhg = Qh + ((size_t)bh * Lc + q0) * DKc;
    const bf16* Qlg = Ql + ((size_t)bh * Lc + q0) * DKc;
    const bf16* Khg = Kh + (size_t)bh * Lc * DKc;
    const bf16* Klg = Kl + (size_t)bh * Lc * DKc;
    const bf16* Vhg = Vh + (size_t)bh * Lc * DKc;
    const bf16* Vlg = Vl + (size_t)bh * Lc * DKc;

    // ---- Phase S: S[16 x 2048] = Q K^T (bf16x3) ----
    {
        wmma::fragment<wmma::matrix_a, 16, 16, 16, bf16, wmma::row_major> aqh[4], aql[4];
#pragma unroll
        for (int kf = 0; kf < 4; ++kf) {
            wmma::load_matrix_sync(aqh[kf], Qhg + kf * 16, DKc);
            wmma::load_matrix_sync(aql[kf], Qlg + kf * 16, DKc);
        }
#pragma unroll 1
        for (int c = 0; c < 16; ++c) {
            int key0 = c * 128 + warp * 16;
            wmma::fragment<wmma::accumulator, 16, 16, 16, float> acc;
            wmma::fill_fragment(acc, 0.0f);
#pragma unroll
            for (int kf = 0; kf < 4; ++kf) {
                wmma::fragment<wmma::matrix_b, 16, 16, 16, bf16, wmma::col_major> bkh, bkl;
                wmma::load_matrix_sync(bkh, Khg + (size_t)key0 * DKc + kf * 16, DKc);
                wmma::load_matrix_sync(bkl, Klg + (size_t)key0 * DKc + kf * 16, DKc);
                wmma::mma_sync(acc, aql[kf], bkh, acc);
                wmma::mma_sync(acc, aqh[kf], bkl, acc);
                wmma::mma_sync(acc, aqh[kf], bkh, acc);
            }
            wmma::store_matrix_sync(&Ssh[key0], acc, SP, wmma::mem_row_major);
        }
    }
    __syncthreads();

    // ---- mask + scale ----
    {
        const int* mbase = maskp + ((size_t)b * Lc + q0) * Lc;
#pragma unroll 4
        for (int f = t; f < 16 * 512; f += 256) {
            int row = f >> 9, c4 = f & 511;
            float4 s = *(float4*)&Ssh[row * SP + c4 * 4];
            int4  mv = *(const int4*)&mbase[(size_t)row * Lc + c4 * 4];
            s.x = mv.x ? s.x * 0.125f : NEGF;
            s.y = mv.y ? s.y * 0.125f : NEGF;
            s.z = mv.z ? s.z * 0.125f : NEGF;
            s.w = mv.w ? s.w * 0.125f : NEGF;
            *(float4*)&Ssh[row * SP + c4 * 4] = s;
        }
    }
    __syncthreads();

    // ---- entmax15 (Newton on tau), emit P hi/lo bf16 ----
    for (int r = 0; r < 2; ++r) {
        int qi = warp * 2 + r;
        float* Srow = &Ssh[qi * SP];
        float z[64];
        float mx = NEGF;
#pragma unroll
        for (int u = 0; u < 64; ++u) {
            z[u] = Srow[lane + 32 * u];
            mx = fmaxf(mx, z[u]);
        }
#pragma unroll
        for (int off = 16; off; off >>= 1)
            mx = fmaxf(mx, __shfl_xor_sync(0xffffffffu, mx, off));
#pragma unroll
        for (int u = 0; u < 64; ++u) z[u] = (z[u] - mx) * 0.5f;

        float tau = -1.0f;
#pragma unroll 1
        for (int it = 0; it < 8; ++it) {
            float s = 0.f, s1 = 0.f;
#pragma unroll
            for (int u = 0; u < 64; ++u) {
                float d = fmaxf(z[u] - tau, 0.f);
                s  = fmaf(d, d, s);
                s1 += d;
            }
#pragma unroll
            for (int off = 16; off; off >>= 1) {
                s  += __shfl_xor_sync(0xffffffffu, s,  off);
                s1 += __shfl_xor_sync(0xffffffffu, s1, off);
            }
            tau += (s - 1.0f) / (2.0f * s1);
        }
        bf16* ph = (bf16*)Srow;                 // in-place: z fully in regs
        bf16* pl = PloS + qi * PLOP;
#pragma unroll
        for (int u = 0; u < 64; ++u) {
            int k = lane + 32 * u;
            float d = fmaxf(z[u] - tau, 0.f);
            float p = d * d;
            bf16 hh, ll;
            split1(p, hh, ll);
            ph[k] = hh;
            pl[k] = ll;
        }
    }
    __syncthreads();

    // ---- Phase PV: out[16 x 64] = P V (bf16x3), split-K over 2 warp-halves ----
    {
        int khalf = warp >> 2;
        int d0    = (warp & 3) * 16;
        const bf16* PhiS = (const bf16*)Ssh;    // ld = 2*SP
        wmma::fragment<wmma::accumulator, 16, 16, 16, float> acc;
        wmma::fill_fragment(acc, 0.0f);
#pragma unroll 2
        for (int kf = 0; kf < 64; ++kf) {
            int k0 = khalf * 1024 + kf * 16;
            wmma::fragment<wmma::matrix_a, 16, 16, 16, bf16, wmma::row_major> aph, apl;
            wmma::load_matrix_sync(aph, PhiS + k0, 2 * SP);
            wmma::load_matrix_sync(apl, PloS + k0, PLOP);
            wmma::fragment<wmma::matrix_b, 16, 16, 16, bf16, wmma::row_major> bvh, bvl;
            wmma::load_matrix_sync(bvh, Vhg + (size_t)k0 * DKc + d0, DKc);
            wmma::load_matrix_sync(bvl, Vlg + (size_t)k0 * DKc + d0, DKc);
            wmma::mma_sync(acc, apl, bvh, acc);
            wmma::mma_sync(acc, aph, bvl, acc);
            wmma::mma_sync(acc, aph, bvh, acc);
        }
        wmma::store_matrix_sync(&Rsh[khalf * 16 * RST + d0], acc, RST, wmma::mem_row_major);
    }
    __syncthreads();

    // ---- reduce halves + write AO hi/lo ----
    {
        int qi = t >> 4;
        int c4 = t & 15;
        float4 r0 = *(float4*)&Rsh[qi * RST + c4 * 4];
        float4 r1 = *(float4*)&Rsh[16 * RST + qi * RST + c4 * 4];
        float4 o;
        o.x = r0.x + r1.x; o.y = r0.y + r1.y; o.z = r0.z + r1.z; o.w = r0.w + r1.w;
        size_t base = ((size_t)b * Lc + q0 + qi) * Dc + h * DKc + c4 * 4;
        bf16 h0, h1, h2, h3, l0, l1, l2, l3;
        split1(o.x, h0, l0); split1(o.y, h1, l1);
        split1(o.z, h2, l2); split1(o.w, h3, l3);
        *(__nv_bfloat162*)&AOh[base]     = __nv_bfloat162(h0, h1);
        *(__nv_bfloat162*)&AOh[base + 2] = __nv_bfloat162(h2, h3);
        *(__nv_bfloat162*)&AOl[base]     = __nv_bfloat162(l0, l1);
        *(__nv_bfloat162*)&AOl[base + 2] = __nv_bfloat162(l2, l3);
    }
}

// ---------------------------------------------------------------------------
// Launch
// ---------------------------------------------------------------------------
extern "C" void kernel_launch(void* const* d_in, const int* in_sizes, int n_in,
                              void* d_out, int out_size)
{
    const float* q    = (const float*)d_in[0];
    const float* k    = (const float*)d_in[1];
    const float* v    = (const float*)d_in[2];
    const int*   mask = (const int*)  d_in[3];
    const float* w_q  = (const float*)d_in[4];
    const float* w_k  = (const float*)d_in[5];
    const float* w_v  = (const float*)d_in[6];
    const float* w_o  = (const float*)d_in[7];
    float* out = (float*)d_out;

    bf16 *qh,*ql,*kh,*kl,*vh,*vl;
    bf16 *wqh,*wql,*wkh,*wkl,*wvh,*wvl,*woh,*wol;
    bf16 *Qh,*Ql,*Kh,*Kl,*Vh,*Vl,*aoh,*aol;
    cudaGetSymbolAddress((void**)&qh, g_qh);   cudaGetSymbolAddress((void**)&ql, g_ql);
    cudaGetSymbolAddress((void**)&kh, g_kh);   cudaGetSymbolAddress((void**)&kl, g_kl);
    cudaGetSymbolAddress((void**)&vh, g_vh);   cudaGetSymbolAddress((void**)&vl, g_vl);
    cudaGetSymbolAddress((void**)&wqh, g_wqh); cudaGetSymbolAddress((void**)&wql, g_wql);
    cudaGetSymbolAddress((void**)&wkh, g_wkh); cudaGetSymbolAddress((void**)&wkl, g_wkl);
    cudaGetSymbolAddress((void**)&wvh, g_wvh); cudaGetSymbolAddress((void**)&wvl, g_wvl);
    cudaGetSymbolAddress((void**)&woh, g_woh); cudaGetSymbolAddress((void**)&wol, g_wol);
    cudaGetSymbolAddress((void**)&Qh, g_Qh);   cudaGetSymbolAddress((void**)&Ql, g_Ql);
    cudaGetSymbolAddress((void**)&Kh, g_Kh);   cudaGetSymbolAddress((void**)&Kl, g_Kl);
    cudaGetSymbolAddress((void**)&Vh, g_Vh);   cudaGetSymbolAddress((void**)&Vl, g_Vl);
    cudaGetSymbolAddress((void**)&aoh, g_aoh); cudaGetSymbolAddress((void**)&aol, g_aol);

    split_bf16<<<NEL / 1024, 256>>>(q, qh, ql, NEL);
    split_bf16<<<NEL / 1024, 256>>>(k, kh, kl, NEL);
    split_bf16<<<NEL / 1024, 256>>>(v, vh, vl, NEL);
    split_bf16<<<NW / 1024, 256>>>(w_q, wqh, wql, NW);
    split_bf16<<<NW / 1024, 256>>>(w_k, wkh, wkl, NW);
    split_bf16<<<NW / 1024, 256>>>(w_v, wvh, wvl, NW);
    split_bf16<<<NW / 1024, 256>>>(w_o, woh, wol, NW);

    cudaFuncSetAttribute(gemm_bf16x3,
                         cudaFuncAttributeMaxDynamicSharedMemorySize, GEMM_SMEM);
    dim3 gg(Dc / 128, (Bc * Lc) / 128);       // (8, 32)

    gemm_bf16x3<<<gg, 256, GEMM_SMEM>>>(qh, ql, wqh, wql, nullptr, Qh, Ql, 1);
    gemm_bf16x3<<<gg, 256, GEMM_SMEM>>>(kh, kl, wkh, wkl, nullptr, Kh, Kl, 1);
    gemm_bf16x3<<<gg, 256, GEMM_SMEM>>>(vh, vl, wvh, wvl, nullptr, Vh, Vl, 1);

    cudaFuncSetAttribute(attn_entmax_kernel,
                         cudaFuncAttributeMaxDynamicSharedMemorySize, ATT_SMEM);
    attn_entmax_kernel<<<dim3(Lc / 16, Hc, Bc), 256, ATT_SMEM>>>(
        Qh, Ql, Kh, Kl, Vh, Vl, mask, aoh, aol);

    gemm_bf16x3<<<gg, 256, GEMM_SMEM>>>(aoh, aol, woh, wol, out, nullptr, nullptr, 0);
}